// round 1
// baseline (speedup 1.0000x reference)
#include <cuda_runtime.h>
#include <math.h>

#define NN 60000
#define NE 119998
#define NP 59999
#define HD 256
#define FEAT 160
#define TLOG (NN + NP)

// ---------------- scratch (__device__ globals: allocation-free) -------------
__device__ float g_feats[(size_t)NE * FEAT];
__device__ float g_msg  [(size_t)NE * HD];
__device__ float g_suv  [(size_t)NE * HD];
__device__ float g_r    [(size_t)NE * HD];
__device__ float g_rdash[(size_t)NE * HD];
__device__ float g_z    [(size_t)NE * HD];
__device__ float g_aggr [(size_t)NN * HD];
__device__ float g_xg   [(size_t)NN * HD];
__device__ float g_h1   [(size_t)NN * 512];
__device__ float g_xedge[(size_t)NP * 512];
__device__ float g_logits[TLOG];
__device__ float g_red[2];

// ---------------- gather: feats[e] = [x[tgt[e]] | edge_attr[e]] -------------
__global__ void featsk(const float* __restrict__ x, const float* __restrict__ ea,
                       const int* __restrict__ ei) {
    int i = blockIdx.x * blockDim.x + threadIdx.x;
    if (i >= NE * 40) return;
    int e = i / 40;
    int q = i - e * 40;
    float4 v;
    if (q < 32) {
        int t = ei[NE + e];
        v = ((const float4*)x)[(size_t)t * 32 + q];
    } else {
        v = ((const float4*)ea)[(size_t)e * 8 + (q - 32)];
    }
    ((float4*)g_feats)[(size_t)e * 40 + q] = v;
}

// ---------------- s_uv[e] = sum over valid nbrs of msg[idx-1] ---------------
__global__ void suvk(const int* __restrict__ nbr) {
    int i = blockIdx.x * blockDim.x + threadIdx.x;
    if (i >= NE * 64) return;
    int e = i >> 6, q = i & 63;
    const float4* m4 = (const float4*)g_msg;
    float4 acc = make_float4(0.f, 0.f, 0.f, 0.f);
#pragma unroll
    for (int j = 0; j < 3; ++j) {
        int idx = nbr[3 * (size_t)e + j];
        if (idx > 0) {
            float4 v = m4[(size_t)(idx - 1) * 64 + q];
            acc.x += v.x; acc.y += v.y; acc.z += v.z; acc.w += v.w;
        }
    }
    ((float4*)g_suv)[i] = acc;
}

// ---------------- r_dash[e] = sum over valid nbrs of r[idx-1]*msg[idx-1] ----
__global__ void rdashk(const int* __restrict__ nbr) {
    int i = blockIdx.x * blockDim.x + threadIdx.x;
    if (i >= NE * 64) return;
    int e = i >> 6, q = i & 63;
    const float4* m4 = (const float4*)g_msg;
    const float4* r4 = (const float4*)g_r;
    float4 acc = make_float4(0.f, 0.f, 0.f, 0.f);
#pragma unroll
    for (int j = 0; j < 3; ++j) {
        int idx = nbr[3 * (size_t)e + j];
        if (idx > 0) {
            size_t o = (size_t)(idx - 1) * 64 + q;
            float4 g = m4[o];
            float4 rr = r4[o];
            acc.x = fmaf(rr.x, g.x, acc.x);
            acc.y = fmaf(rr.y, g.y, acc.y);
            acc.z = fmaf(rr.z, g.z, acc.z);
            acc.w = fmaf(rr.w, g.w, acc.w);
        }
    }
    ((float4*)g_rdash)[i] = acc;
}

// ---------------- aggr[tgt[e]] += msg[e] ------------------------------------
__global__ void aggrk(const int* __restrict__ ei) {
    int i = blockIdx.x * blockDim.x + threadIdx.x;
    if (i >= NE * HD) return;
    int e = i >> 8, h = i & 255;
    int t = ei[NE + e];
    atomicAdd(&g_aggr[(size_t)t * HD + h], g_msg[i]);
}

// ---------------- x_edge[p] = [|xg[u]-xg[v]| , xg[u]+xg[v]] -----------------
__global__ void xedgek(const int* __restrict__ ei) {
    int i = blockIdx.x * blockDim.x + threadIdx.x;
    if (i >= NP * 64) return;
    int p = i >> 6, q = i & 63;
    int u = ei[2 * p];
    int v = ei[NE + 2 * p];
    const float4* X = (const float4*)g_xg;
    float4 a = X[(size_t)u * 64 + q];
    float4 b = X[(size_t)v * 64 + q];
    float4* out = (float4*)g_xedge;
    out[(size_t)p * 128 + q] =
        make_float4(fabsf(a.x - b.x), fabsf(a.y - b.y), fabsf(a.z - b.z), fabsf(a.w - b.w));
    out[(size_t)p * 128 + 64 + q] =
        make_float4(a.x + b.x, a.y + b.y, a.z + b.z, a.w + b.w);
}

// ---------------- generic fused GEMM: C = act(A1@B1^T + A2@B2^T + bias) -----
// A row-major [M,K], B row-major [Nout, ldb] (we use columns [0,K) of each row)
// mode: 0=sigmoid  1=GRU combine ((1-z)*suv + z*tanh(v))  2=relu  3=none
#define BM 128
#define BN 128
#define BK 16
#define SPAD 4

__global__ void __launch_bounds__(256) gemm2k(
    const float* __restrict__ A1, int K1, const float* __restrict__ B1, int ldb1,
    const float* __restrict__ A2, int K2, const float* __restrict__ B2, int ldb2,
    const float* __restrict__ bias, float* __restrict__ C, int M, int N, int mode,
    const float* __restrict__ zb, const float* __restrict__ sb)
{
    __shared__ float As[BK][BM + SPAD];
    __shared__ float Bs[BK][BN + SPAD];
    const int tid  = threadIdx.x;
    const int m0   = blockIdx.x * BM;
    const int n0   = blockIdx.y * BN;
    const int lr   = tid >> 2;          // 0..63
    const int lc   = (tid & 3) << 2;    // 0,4,8,12
    const int trow = (tid >> 4) << 3;   // 0..120
    const int tcol = (tid & 15) << 3;   // 0..120

    float acc[8][8];
#pragma unroll
    for (int i = 0; i < 8; ++i)
#pragma unroll
        for (int j = 0; j < 8; ++j) acc[i][j] = 0.f;

#pragma unroll 1
    for (int pass = 0; pass < 2; ++pass) {
        const float* A = pass ? A2 : A1;
        const float* B = pass ? B2 : B1;
        const int K    = pass ? K2 : K1;
        const int ldb  = pass ? ldb2 : ldb1;
        if (K == 0) continue;
        for (int k0 = 0; k0 < K; k0 += BK) {
#pragma unroll
            for (int h = 0; h < 2; ++h) {
                int r  = lr + h * 64;
                int gm = m0 + r;
                float4 v = make_float4(0.f, 0.f, 0.f, 0.f);
                if (gm < M) v = *(const float4*)(A + (size_t)gm * K + (k0 + lc));
                As[lc + 0][r] = v.x; As[lc + 1][r] = v.y;
                As[lc + 2][r] = v.z; As[lc + 3][r] = v.w;
                int gn = n0 + r;
                float4 w = *(const float4*)(B + (size_t)gn * ldb + (k0 + lc));
                Bs[lc + 0][r] = w.x; Bs[lc + 1][r] = w.y;
                Bs[lc + 2][r] = w.z; Bs[lc + 3][r] = w.w;
            }
            __syncthreads();
#pragma unroll
            for (int kk = 0; kk < BK; ++kk) {
                float a[8], b[8];
                *(float4*)&a[0] = *(const float4*)&As[kk][trow];
                *(float4*)&a[4] = *(const float4*)&As[kk][trow + 4];
                *(float4*)&b[0] = *(const float4*)&Bs[kk][tcol];
                *(float4*)&b[4] = *(const float4*)&Bs[kk][tcol + 4];
#pragma unroll
                for (int i = 0; i < 8; ++i)
#pragma unroll
                    for (int j = 0; j < 8; ++j)
                        acc[i][j] = fmaf(a[i], b[j], acc[i][j]);
            }
            __syncthreads();
        }
    }

#pragma unroll
    for (int i = 0; i < 8; ++i) {
        int gm = m0 + trow + i;
        if (gm >= M) break;
#pragma unroll
        for (int j = 0; j < 8; ++j) {
            int gn = n0 + tcol + j;
            float v = acc[i][j] + bias[gn];
            size_t idx = (size_t)gm * N + gn;
            if (mode == 0) {
                v = 1.f / (1.f + expf(-v));
            } else if (mode == 1) {
                float zz = zb[idx];
                v = (1.f - zz) * sb[idx] + zz * tanhf(v);
            } else if (mode == 2) {
                v = fmaxf(v, 0.f);
            }
            C[idx] = v;
        }
    }
}

// ---------------- head dot: logits[row] = relu_h1[row] . w + b --------------
__global__ void dotk(const float* __restrict__ w, const float* __restrict__ bptr,
                     float* __restrict__ out, int rows) {
    int gw = (blockIdx.x * blockDim.x + threadIdx.x) >> 5;
    int lane = threadIdx.x & 31;
    if (gw >= rows) return;
    const float* hrow = g_h1 + (size_t)gw * 512;
    float s = 0.f;
#pragma unroll
    for (int k = 0; k < 16; ++k) s = fmaf(hrow[lane + 32 * k], w[lane + 32 * k], s);
#pragma unroll
    for (int o = 16; o; o >>= 1) s += __shfl_down_sync(0xffffffffu, s, o);
    if (lane == 0) out[gw] = s + bptr[0];
}

// ---------------- softmax over all TLOG logits ------------------------------
__global__ void soft1k() {
    __shared__ float sm[1024];
    int tid = threadIdx.x;
    float mx = -1e30f;
    for (int i = tid; i < TLOG; i += 1024) mx = fmaxf(mx, g_logits[i]);
    sm[tid] = mx;
    __syncthreads();
    for (int s = 512; s > 0; s >>= 1) {
        if (tid < s) sm[tid] = fmaxf(sm[tid], sm[tid + s]);
        __syncthreads();
    }
    float gmax = sm[0];
    __syncthreads();
    float sum = 0.f;
    for (int i = tid; i < TLOG; i += 1024) sum += expf(g_logits[i] - gmax);
    sm[tid] = sum;
    __syncthreads();
    for (int s = 512; s > 0; s >>= 1) {
        if (tid < s) sm[tid] += sm[tid + s];
        __syncthreads();
    }
    if (tid == 0) { g_red[0] = gmax; g_red[1] = sm[0]; }
}

__global__ void soft2k(float* __restrict__ out) {
    int i = blockIdx.x * blockDim.x + threadIdx.x;
    if (i < TLOG) out[i] = expf(g_logits[i] - g_red[0]) / g_red[1];
}

// ---------------------------------------------------------------------------
extern "C" void kernel_launch(void* const* d_in, const int* in_sizes, int n_in,
                              void* d_out, int out_size) {
    (void)in_sizes; (void)n_in; (void)out_size;
    const float* x      = (const float*)d_in[0];
    const float* ea     = (const float*)d_in[1];
    const int*   ei     = (const int*)d_in[2];   // [2, NE] int32 (jax default x64 off)
    const int*   nbr    = (const int*)d_in[3];   // [NE, 3] int32
    const float* Wz_w   = (const float*)d_in[4];
    const float* Wz_b   = (const float*)d_in[5];
    const float* Wr_w   = (const float*)d_in[6];
    const float* Wr_b   = (const float*)d_in[7];
    const float* W_w    = (const float*)d_in[8];
    const float* U_w    = (const float*)d_in[9];
    const float* U_b    = (const float*)d_in[10];
    const float* mlp_w  = (const float*)d_in[11];
    const float* mlp_b  = (const float*)d_in[12];
    const float* nc1_w  = (const float*)d_in[13];
    const float* nc1_b  = (const float*)d_in[14];
    const float* nc2_w  = (const float*)d_in[15];
    const float* nc2_b  = (const float*)d_in[16];
    const float* ec1_w  = (const float*)d_in[17];
    const float* ec1_b  = (const float*)d_in[18];
    const float* ec2_w  = (const float*)d_in[19];
    const float* ec2_b  = (const float*)d_in[20];
    float* out = (float*)d_out;

    float *feats, *msg, *suv, *r, *rdash, *z, *aggr, *xg, *h1, *xedge, *logits;
    cudaGetSymbolAddress((void**)&feats,  g_feats);
    cudaGetSymbolAddress((void**)&msg,    g_msg);
    cudaGetSymbolAddress((void**)&suv,    g_suv);
    cudaGetSymbolAddress((void**)&r,      g_r);
    cudaGetSymbolAddress((void**)&rdash,  g_rdash);
    cudaGetSymbolAddress((void**)&z,      g_z);
    cudaGetSymbolAddress((void**)&aggr,   g_aggr);
    cudaGetSymbolAddress((void**)&xg,     g_xg);
    cudaGetSymbolAddress((void**)&h1,     g_h1);
    cudaGetSymbolAddress((void**)&xedge,  g_xedge);
    cudaGetSymbolAddress((void**)&logits, g_logits);

    cudaMemsetAsync(msg, 0, (size_t)NE * HD * sizeof(float), 0);
    featsk<<<(NE * 40 + 255) / 256, 256>>>(x, ea, ei);

    dim3 ge2((NE + BM - 1) / BM, HD / BN);
    for (int l = 0; l < 4; ++l) {
        const float* Wz = Wz_w + (size_t)l * HD * 416;
        const float* Wr = Wr_w + (size_t)l * HD * 416;
        const float* Ww = W_w  + (size_t)l * HD * 160;
        const float* Uw = U_w  + (size_t)l * HD * HD;

        suvk<<<(NE * 64 + 255) / 256, 256>>>(nbr);
        // z = sigmoid([feats|s_uv] @ Wz^T + b)
        gemm2k<<<ge2, 256>>>(feats, 160, Wz, 416, suv, 256, Wz + 160, 416,
                             Wz_b + (size_t)l * HD, z, NE, HD, 0, nullptr, nullptr);
        // r = sigmoid([feats|msg] @ Wr^T + b)
        gemm2k<<<ge2, 256>>>(feats, 160, Wr, 416, msg, 256, Wr + 160, 416,
                             Wr_b + (size_t)l * HD, r, NE, HD, 0, nullptr, nullptr);
        rdashk<<<(NE * 64 + 255) / 256, 256>>>(nbr);
        // msg = (1-z)*s_uv + z*tanh(feats@W^T + r_dash@U^T + U_b)
        gemm2k<<<ge2, 256>>>(feats, 160, Ww, 160, rdash, 256, Uw, 256,
                             U_b + (size_t)l * HD, msg, NE, HD, 1, z, suv);
    }

    cudaMemsetAsync(aggr, 0, (size_t)NN * HD * sizeof(float), 0);
    aggrk<<<(NE * HD + 255) / 256, 256>>>(ei);

    // xg = relu([x|aggr] @ mlp^T + b)
    dim3 gxg((NN + BM - 1) / BM, HD / BN);
    gemm2k<<<gxg, 256>>>(x, 128, mlp_w, 384, aggr, 256, mlp_w + 128, 384,
                         mlp_b, xg, NN, HD, 2, nullptr, nullptr);

    // node head
    dim3 gn1((NN + BM - 1) / BM, 512 / BN);
    gemm2k<<<gn1, 256>>>(xg, 256, nc1_w, 256, nullptr, 0, nullptr, 0,
                         nc1_b, h1, NN, 512, 2, nullptr, nullptr);
    dotk<<<(NN * 32 + 255) / 256, 256>>>(nc2_w, nc2_b, logits, NN);

    // edge head
    xedgek<<<(NP * 64 + 255) / 256, 256>>>(ei);
    dim3 ge1((NP + BM - 1) / BM, 512 / BN);
    gemm2k<<<ge1, 256>>>(xedge, 512, ec1_w, 512, nullptr, 0, nullptr, 0,
                         ec1_b, h1, NP, 512, 2, nullptr, nullptr);
    dotk<<<(NP * 32 + 255) / 256, 256>>>(ec2_w, ec2_b, logits + NN, NP);

    // global softmax
    soft1k<<<1, 1024>>>();
    soft2k<<<(TLOG + 255) / 256, 256>>>(out);
}

// round 5
// speedup vs baseline: 1.5761x; 1.5761x over previous
#include <cuda_runtime.h>
#include <cuda_bf16.h>
#include <cstdint>
#include <math.h>

#define NN 60000
#define NE 119998
#define NP 59999
#define TLOG (NN + NP)

typedef __nv_bfloat16 bf16;

// ---------------- fp32 scratch --------------------------------------------
__device__ float g_feats[(size_t)NE * 160];
__device__ float g_msg  [(size_t)NE * 256];
__device__ float g_suv  [(size_t)NE * 256];
__device__ float g_r    [(size_t)NE * 256];
__device__ float g_z    [(size_t)NE * 256];
__device__ float g_aggr [(size_t)NN * 256];
__device__ float g_xg   [(size_t)NN * 256];
__device__ float g_h1   [(size_t)NN * 512];
__device__ float g_logits[TLOG];
__device__ float g_red[2];

// ---------------- bf16 hi/lo scratch (one big arena) -----------------------
#define SZ_FEATS ((size_t)NE * 192)
#define SZ_E256  ((size_t)NE * 256)
#define SZ_X     ((size_t)NN * 128)
#define SZ_N256  ((size_t)NN * 256)
#define SZ_XE    ((size_t)NP * 512)

constexpr size_t O_FEATS_H = 0;
constexpr size_t O_FEATS_L = O_FEATS_H + SZ_FEATS;
constexpr size_t O_MSG_H   = O_FEATS_L + SZ_FEATS;
constexpr size_t O_MSG_L   = O_MSG_H + SZ_E256;
constexpr size_t O_SUV_H   = O_MSG_L + SZ_E256;
constexpr size_t O_SUV_L   = O_SUV_H + SZ_E256;
constexpr size_t O_RD_H    = O_SUV_L + SZ_E256;
constexpr size_t O_RD_L    = O_RD_H + SZ_E256;
constexpr size_t O_X_H     = O_RD_L + SZ_E256;
constexpr size_t O_X_L     = O_X_H + SZ_X;
constexpr size_t O_AG_H    = O_X_L + SZ_X;
constexpr size_t O_AG_L    = O_AG_H + SZ_N256;
constexpr size_t O_XG_H    = O_AG_L + SZ_N256;
constexpr size_t O_XG_L    = O_XG_H + SZ_N256;
constexpr size_t O_XE_H    = O_XG_L + SZ_N256;
constexpr size_t O_XE_L    = O_XE_H + SZ_XE;
constexpr size_t O_WZ1_H   = O_XE_L + SZ_XE;
constexpr size_t O_WZ1_L   = O_WZ1_H + 4 * 256 * 192;
constexpr size_t O_WZ2_H   = O_WZ1_L + 4 * 256 * 192;
constexpr size_t O_WZ2_L   = O_WZ2_H + 4 * 256 * 256;
constexpr size_t O_WR1_H   = O_WZ2_L + 4 * 256 * 256;
constexpr size_t O_WR1_L   = O_WR1_H + 4 * 256 * 192;
constexpr size_t O_WR2_H   = O_WR1_L + 4 * 256 * 192;
constexpr size_t O_WR2_L   = O_WR2_H + 4 * 256 * 256;
constexpr size_t O_WW_H    = O_WR2_L + 4 * 256 * 256;
constexpr size_t O_WW_L    = O_WW_H + 4 * 256 * 192;
constexpr size_t O_UW_H    = O_WW_L + 4 * 256 * 192;
constexpr size_t O_UW_L    = O_UW_H + 4 * 256 * 256;
constexpr size_t O_M1_H    = O_UW_L + 4 * 256 * 256;
constexpr size_t O_M1_L    = O_M1_H + 256 * 128;
constexpr size_t O_M2_H    = O_M1_L + 256 * 128;
constexpr size_t O_M2_L    = O_M2_H + 256 * 256;
constexpr size_t O_N1_H    = O_M2_L + 256 * 256;
constexpr size_t O_N1_L    = O_N1_H + 512 * 256;
constexpr size_t O_E1_H    = O_N1_L + 512 * 256;
constexpr size_t O_E1_L    = O_E1_H + 512 * 512;
constexpr size_t BF_TOTAL  = O_E1_L + 512 * 512;

__device__ bf16 g_bf[BF_TOTAL];

// ---------------- helpers --------------------------------------------------
__device__ __forceinline__ uint32_t s2u(const void* p) {
    uint32_t a;
    asm("{ .reg .u64 t; cvta.to.shared.u64 t, %1; cvt.u32.u64 %0, t; }" : "=r"(a) : "l"(p));
    return a;
}

__device__ __forceinline__ void mma16816(float* c, const uint32_t* a, const uint32_t* b) {
    asm volatile(
        "mma.sync.aligned.m16n8k16.row.col.f32.bf16.bf16.f32 "
        "{%0,%1,%2,%3}, {%4,%5,%6,%7}, {%8,%9}, {%0,%1,%2,%3};"
        : "+f"(c[0]), "+f"(c[1]), "+f"(c[2]), "+f"(c[3])
        : "r"(a[0]), "r"(a[1]), "r"(a[2]), "r"(a[3]), "r"(b[0]), "r"(b[1]));
}

__device__ __forceinline__ void store_hl4(bf16* hp, bf16* lp, float4 v) {
    bf16 h0 = __float2bfloat16(v.x), h1 = __float2bfloat16(v.y);
    bf16 h2 = __float2bfloat16(v.z), h3 = __float2bfloat16(v.w);
    bf16 l0 = __float2bfloat16(v.x - __bfloat162float(h0));
    bf16 l1 = __float2bfloat16(v.y - __bfloat162float(h1));
    bf16 l2 = __float2bfloat16(v.z - __bfloat162float(h2));
    bf16 l3 = __float2bfloat16(v.w - __bfloat162float(h3));
    ((__nv_bfloat162*)hp)[0] = __halves2bfloat162(h0, h1);
    ((__nv_bfloat162*)hp)[1] = __halves2bfloat162(h2, h3);
    ((__nv_bfloat162*)lp)[0] = __halves2bfloat162(l0, l1);
    ((__nv_bfloat162*)lp)[1] = __halves2bfloat162(l2, l3);
}

__device__ __forceinline__ void store_hl2(bf16* hp, bf16* lp, float v0, float v1) {
    bf16 h0 = __float2bfloat16(v0), h1 = __float2bfloat16(v1);
    bf16 l0 = __float2bfloat16(v0 - __bfloat162float(h0));
    bf16 l1 = __float2bfloat16(v1 - __bfloat162float(h1));
    *(__nv_bfloat162*)hp = __halves2bfloat162(h0, h1);
    *(__nv_bfloat162*)lp = __halves2bfloat162(l0, l1);
}

// ---------------- small kernels --------------------------------------------
__global__ void featsk(const float* __restrict__ x, const float* __restrict__ ea,
                       const int* __restrict__ ei) {
    int i = blockIdx.x * blockDim.x + threadIdx.x;
    if (i >= NE * 40) return;
    int e = i / 40;
    int q = i - e * 40;
    float4 v;
    if (q < 32) {
        int t = ei[NE + e];
        v = ((const float4*)x)[(size_t)t * 32 + q];
    } else {
        v = ((const float4*)ea)[(size_t)e * 8 + (q - 32)];
    }
    ((float4*)g_feats)[(size_t)e * 40 + q] = v;
}

__global__ void suvk(const int* __restrict__ nbr, bf16* __restrict__ sh, bf16* __restrict__ sl) {
    int i = blockIdx.x * blockDim.x + threadIdx.x;
    if (i >= NE * 64) return;
    int e = i >> 6, q = i & 63;
    const float4* m4 = (const float4*)g_msg;
    float4 acc = make_float4(0.f, 0.f, 0.f, 0.f);
#pragma unroll
    for (int j = 0; j < 3; ++j) {
        int idx = nbr[3 * (size_t)e + j];
        if (idx > 0) {
            float4 v = m4[(size_t)(idx - 1) * 64 + q];
            acc.x += v.x; acc.y += v.y; acc.z += v.z; acc.w += v.w;
        }
    }
    ((float4*)g_suv)[i] = acc;
    size_t o = (size_t)e * 256 + q * 4;
    store_hl4(sh + o, sl + o, acc);
}

__global__ void rdashk(const int* __restrict__ nbr, bf16* __restrict__ rh, bf16* __restrict__ rl) {
    int i = blockIdx.x * blockDim.x + threadIdx.x;
    if (i >= NE * 64) return;
    int e = i >> 6, q = i & 63;
    const float4* m4 = (const float4*)g_msg;
    const float4* r4 = (const float4*)g_r;
    float4 acc = make_float4(0.f, 0.f, 0.f, 0.f);
#pragma unroll
    for (int j = 0; j < 3; ++j) {
        int idx = nbr[3 * (size_t)e + j];
        if (idx > 0) {
            size_t o = (size_t)(idx - 1) * 64 + q;
            float4 g = m4[o];
            float4 rr = r4[o];
            acc.x = fmaf(rr.x, g.x, acc.x);
            acc.y = fmaf(rr.y, g.y, acc.y);
            acc.z = fmaf(rr.z, g.z, acc.z);
            acc.w = fmaf(rr.w, g.w, acc.w);
        }
    }
    size_t o = (size_t)e * 256 + q * 4;
    store_hl4(rh + o, rl + o, acc);
}

__global__ void aggrk(const int* __restrict__ ei) {
    int i = blockIdx.x * blockDim.x + threadIdx.x;
    if (i >= NE * 256) return;
    int e = i >> 8, h = i & 255;
    int t = ei[NE + e];
    atomicAdd(&g_aggr[(size_t)t * 256 + h], g_msg[i]);
}

__global__ void xedgek(const int* __restrict__ ei, bf16* __restrict__ xh, bf16* __restrict__ xl) {
    int i = blockIdx.x * blockDim.x + threadIdx.x;
    if (i >= NP * 64) return;
    int p = i >> 6, q = i & 63;
    int u = ei[2 * p];
    int v = ei[NE + 2 * p];
    const float4* X = (const float4*)g_xg;
    float4 a = X[(size_t)u * 64 + q];
    float4 b = X[(size_t)v * 64 + q];
    size_t o = (size_t)p * 512 + q * 4;
    store_hl4(xh + o, xl + o,
        make_float4(fabsf(a.x - b.x), fabsf(a.y - b.y), fabsf(a.z - b.z), fabsf(a.w - b.w)));
    store_hl4(xh + o + 256, xl + o + 256,
        make_float4(a.x + b.x, a.y + b.y, a.z + b.z, a.w + b.w));
}

// pad-convert fp32 -> bf16 hi/lo
__global__ void convk(const float* __restrict__ src, long long total, int K, int rowStride,
                      int colOff, int Kp, bf16* __restrict__ hi, bf16* __restrict__ lo) {
    long long i = (long long)blockIdx.x * blockDim.x + threadIdx.x;
    if (i >= total) return;
    int k = (int)(i % Kp);
    long long row = i / Kp;
    float v = (k < K) ? src[row * rowStride + colOff + k] : 0.f;
    bf16 h = __float2bfloat16(v);
    hi[i] = h;
    lo[i] = __float2bfloat16(v - __bfloat162float(h));
}

// ---------------- split-bf16 mma.sync GEMM ----------------------------------
// C[M,N] = act(A1@B1^T + A2@B2^T + bias). A,B in hi/lo bf16, K padded to 64.
// CTA tile 128(M) x 128(N), K-chunk 64, cp.async double buffer.
// mode 0=sigmoid 1=GRU 2=relu
#define ROWB 144
#define TILEB (128 * ROWB)                 // 18432 per sub-tile
#define STAGE_B (4 * TILEB)                // Ah, Al, Bh, Bl
#define SMEM_DYN (2 * STAGE_B)             // 147456

__global__ void __launch_bounds__(256) gemm_tc(
    const bf16* __restrict__ A1h, const bf16* __restrict__ A1l, int K1p,
    const bf16* __restrict__ B1h, const bf16* __restrict__ B1l,
    const bf16* __restrict__ A2h, const bf16* __restrict__ A2l, int K2p,
    const bf16* __restrict__ B2h, const bf16* __restrict__ B2l,
    const float* __restrict__ bias, float* __restrict__ C, int M, int N, int mode,
    const float* __restrict__ zb, const float* __restrict__ sb,
    bf16* __restrict__ outH, bf16* __restrict__ outL)
{
    extern __shared__ char dsm[];
    const int tid  = threadIdx.x;
    const int warp = tid >> 5;
    const int lane = tid & 31;
    const int g    = lane >> 2;
    const int t    = lane & 3;
    const int wm   = warp & 1;       // 0,1 -> 64-row half
    const int wn   = warp >> 1;      // 0..3 -> 32-col quarter
    const int m0   = blockIdx.x * 128;
    const int n0   = blockIdx.y * 128;

    const int nch1 = K1p >> 6;
    const int nch2 = B2h ? (K2p >> 6) : 0;
    const int nch  = nch1 + nch2;

    // frag-load byte offsets within a stage (A rows / B rows), t*4 folded in
    int aOff0[4], aOff1[4], bOff[4];
#pragma unroll
    for (int mt = 0; mt < 4; ++mt) {
        int row = wm * 64 + mt * 16 + g;
        aOff0[mt] = row * ROWB + t * 4;
        aOff1[mt] = (row + 8) * ROWB + t * 4;
    }
#pragma unroll
    for (int nt = 0; nt < 4; ++nt) {
        int row = wn * 32 + nt * 8 + g;
        bOff[nt] = 2 * TILEB + row * ROWB + t * 4;
    }

    float acc[4][4][4];
#pragma unroll
    for (int i = 0; i < 4; ++i)
#pragma unroll
        for (int j = 0; j < 4; ++j)
#pragma unroll
            for (int k = 0; k < 4; ++k) acc[i][j][k] = 0.f;

    auto issue = [&](int c) {
        const bf16 *Ah, *Al, *Bh, *Bl;
        int lda, kc;
        if (c < nch1) { Ah = A1h; Al = A1l; Bh = B1h; Bl = B1l; lda = K1p; kc = c << 6; }
        else          { Ah = A2h; Al = A2l; Bh = B2h; Bl = B2l; lda = K2p; kc = (c - nch1) << 6; }
        char* dstb = dsm + (c & 1) * STAGE_B;
#pragma unroll 4
        for (int u = tid; u < 4096; u += 256) {
            int which = u >> 10;       // 0 Ah, 1 Al, 2 Bh, 3 Bl
            int rem   = u & 1023;
            int row   = rem >> 3;
            int un    = rem & 7;
            const bf16* sm = (which == 0) ? Ah : (which == 1) ? Al : (which == 2) ? Bh : Bl;
            int sz = 16;
            long long grow;
            if (which < 2) {
                int gm = m0 + row;
                if (gm >= M) { gm = M - 1; sz = 0; }
                grow = gm;
            } else {
                grow = n0 + row;
            }
            const char* src = (const char*)(sm + grow * (long long)lda + kc) + un * 16;
            uint32_t du = s2u(dstb + which * TILEB + row * ROWB + un * 16);
            asm volatile("cp.async.cg.shared.global [%0], [%1], 16, %2;"
                         :: "r"(du), "l"(src), "r"(sz) : "memory");
        }
        asm volatile("cp.async.commit_group;" ::: "memory");
    };

    issue(0);
    for (int c = 0; c < nch; ++c) {
        if (c + 1 < nch) {
            issue(c + 1);
            asm volatile("cp.async.wait_group 1;" ::: "memory");
        } else {
            asm volatile("cp.async.wait_group 0;" ::: "memory");
        }
        __syncthreads();

        const char* base = dsm + (c & 1) * STAGE_B;
#pragma unroll
        for (int ks = 0; ks < 4; ++ks) {
            uint32_t ah[4][4], al[4][4], bh[4][2], bl[4][2];
#pragma unroll
            for (int mt = 0; mt < 4; ++mt) {
                const char* r0 = base + aOff0[mt] + ks * 32;
                const char* r1 = base + aOff1[mt] + ks * 32;
                ah[mt][0] = *(const uint32_t*)(r0);
                ah[mt][1] = *(const uint32_t*)(r1);
                ah[mt][2] = *(const uint32_t*)(r0 + 16);
                ah[mt][3] = *(const uint32_t*)(r1 + 16);
                al[mt][0] = *(const uint32_t*)(r0 + TILEB);
                al[mt][1] = *(const uint32_t*)(r1 + TILEB);
                al[mt][2] = *(const uint32_t*)(r0 + TILEB + 16);
                al[mt][3] = *(const uint32_t*)(r1 + TILEB + 16);
            }
#pragma unroll
            for (int nt = 0; nt < 4; ++nt) {
                const char* rb = base + bOff[nt] + ks * 32;
                bh[nt][0] = *(const uint32_t*)(rb);
                bh[nt][1] = *(const uint32_t*)(rb + 16);
                bl[nt][0] = *(const uint32_t*)(rb + TILEB);
                bl[nt][1] = *(const uint32_t*)(rb + TILEB + 16);
            }
#pragma unroll
            for (int mt = 0; mt < 4; ++mt)
#pragma unroll
                for (int nt = 0; nt < 4; ++nt) {
                    mma16816(acc[mt][nt], ah[mt], bh[nt]);
                    mma16816(acc[mt][nt], ah[mt], bl[nt]);
                    mma16816(acc[mt][nt], al[mt], bh[nt]);
                }
        }
        __syncthreads();
    }

    // ---------------- epilogue ----------------
#pragma unroll
    for (int mt = 0; mt < 4; ++mt) {
        int rg = m0 + wm * 64 + mt * 16 + g;
#pragma unroll
        for (int nt = 0; nt < 4; ++nt) {
            int cn = n0 + wn * 32 + nt * 8 + 2 * t;
            float b0 = bias[cn], b1 = bias[cn + 1];
#pragma unroll
            for (int h = 0; h < 2; ++h) {
                int row = rg + h * 8;
                if (row >= M) continue;
                float v0 = acc[mt][nt][2 * h]     + b0;
                float v1 = acc[mt][nt][2 * h + 1] + b1;
                size_t idx = (size_t)row * N + cn;
                if (mode == 0) {
                    v0 = 1.f / (1.f + expf(-v0));
                    v1 = 1.f / (1.f + expf(-v1));
                } else if (mode == 1) {
                    float z0 = zb[idx], z1 = zb[idx + 1];
                    v0 = (1.f - z0) * sb[idx]     + z0 * tanhf(v0);
                    v1 = (1.f - z1) * sb[idx + 1] + z1 * tanhf(v1);
                } else {
                    v0 = fmaxf(v0, 0.f);
                    v1 = fmaxf(v1, 0.f);
                }
                *(float2*)(C + idx) = make_float2(v0, v1);
                if (outH) store_hl2(outH + idx, outL + idx, v0, v1);
            }
        }
    }
}

// ---------------- head dot + softmax ---------------------------------------
__global__ void dotk(const float* __restrict__ w, const float* __restrict__ bptr,
                     float* __restrict__ out, int rows) {
    int gw = (blockIdx.x * blockDim.x + threadIdx.x) >> 5;
    int lane = threadIdx.x & 31;
    if (gw >= rows) return;
    const float* hrow = g_h1 + (size_t)gw * 512;
    float s = 0.f;
#pragma unroll
    for (int k = 0; k < 16; ++k) s = fmaf(hrow[lane + 32 * k], w[lane + 32 * k], s);
#pragma unroll
    for (int o = 16; o; o >>= 1) s += __shfl_down_sync(0xffffffffu, s, o);
    if (lane == 0) out[gw] = s + bptr[0];
}

__global__ void soft1k() {
    __shared__ float sm[1024];
    int tid = threadIdx.x;
    float mx = -1e30f;
    for (int i = tid; i < TLOG; i += 1024) mx = fmaxf(mx, g_logits[i]);
    sm[tid] = mx;
    __syncthreads();
    for (int s = 512; s > 0; s >>= 1) {
        if (tid < s) sm[tid] = fmaxf(sm[tid], sm[tid + s]);
        __syncthreads();
    }
    float gmax = sm[0];
    __syncthreads();
    float sum = 0.f;
    for (int i = tid; i < TLOG; i += 1024) sum += expf(g_logits[i] - gmax);
    sm[tid] = sum;
    __syncthreads();
    for (int s = 512; s > 0; s >>= 1) {
        if (tid < s) sm[tid] += sm[tid + s];
        __syncthreads();
    }
    if (tid == 0) { g_red[0] = gmax; g_red[1] = sm[0]; }
}

__global__ void soft2k(float* __restrict__ out) {
    int i = blockIdx.x * blockDim.x + threadIdx.x;
    if (i < TLOG) out[i] = expf(g_logits[i] - g_red[0]) / g_red[1];
}

// ---------------------------------------------------------------------------
extern "C" void kernel_launch(void* const* d_in, const int* in_sizes, int n_in,
                              void* d_out, int out_size) {
    (void)in_sizes; (void)n_in; (void)out_size;
    const float* x     = (const float*)d_in[0];
    const float* ea    = (const float*)d_in[1];
    const int*   ei    = (const int*)d_in[2];
    const int*   nbr   = (const int*)d_in[3];
    const float* Wz_w  = (const float*)d_in[4];
    const float* Wz_b  = (const float*)d_in[5];
    const float* Wr_w  = (const float*)d_in[6];
    const float* Wr_b  = (const float*)d_in[7];
    const float* W_w   = (const float*)d_in[8];
    const float* U_w   = (const float*)d_in[9];
    const float* U_b   = (const float*)d_in[10];
    const float* mlp_w = (const float*)d_in[11];
    const float* mlp_b = (const float*)d_in[12];
    const float* nc1_w = (const float*)d_in[13];
    const float* nc1_b = (const float*)d_in[14];
    const float* nc2_w = (const float*)d_in[15];
    const float* nc2_b = (const float*)d_in[16];
    const float* ec1_w = (const float*)d_in[17];
    const float* ec1_b = (const float*)d_in[18];
    const float* ec2_w = (const float*)d_in[19];
    const float* ec2_b = (const float*)d_in[20];
    float* out = (float*)d_out;

    float *feats, *msg, *suv, *r, *z, *aggr, *xg, *h1, *logits;
    bf16* bfb;
    cudaGetSymbolAddress((void**)&feats,  g_feats);
    cudaGetSymbolAddress((void**)&msg,    g_msg);
    cudaGetSymbolAddress((void**)&suv,    g_suv);
    cudaGetSymbolAddress((void**)&r,      g_r);
    cudaGetSymbolAddress((void**)&z,      g_z);
    cudaGetSymbolAddress((void**)&aggr,   g_aggr);
    cudaGetSymbolAddress((void**)&xg,     g_xg);
    cudaGetSymbolAddress((void**)&h1,     g_h1);
    cudaGetSymbolAddress((void**)&logits, g_logits);
    cudaGetSymbolAddress((void**)&bfb,    g_bf);

    cudaFuncSetAttribute(gemm_tc, cudaFuncAttributeMaxDynamicSharedMemorySize, SMEM_DYN);

    bf16 *fH = bfb + O_FEATS_H, *fL = bfb + O_FEATS_L;
    bf16 *mH = bfb + O_MSG_H,  *mL = bfb + O_MSG_L;
    bf16 *sH = bfb + O_SUV_H,  *sL = bfb + O_SUV_L;
    bf16 *rH = bfb + O_RD_H,   *rL = bfb + O_RD_L;
    bf16 *xH = bfb + O_X_H,    *xL = bfb + O_X_L;
    bf16 *aH = bfb + O_AG_H,   *aL = bfb + O_AG_L;
    bf16 *gH = bfb + O_XG_H,   *gL = bfb + O_XG_L;
    bf16 *eH = bfb + O_XE_H,   *eL = bfb + O_XE_L;

    cudaMemsetAsync(msg, 0, (size_t)NE * 256 * 4, 0);
    cudaMemsetAsync(mH, 0, SZ_E256 * 2, 0);
    cudaMemsetAsync(mL, 0, SZ_E256 * 2, 0);

    featsk<<<(NE * 40 + 255) / 256, 256>>>(x, ea, ei);

#define CONV(src, tot, K, stride, off, Kp, hi, lo) \
    convk<<<(int)(((long long)(tot) + 255) / 256), 256>>>(src, (long long)(tot), K, stride, off, Kp, hi, lo)

    CONV(feats, (long long)NE * 192, 160, 160, 0, 192, fH, fL);
    CONV(x, (long long)NN * 128, 128, 128, 0, 128, xH, xL);
    CONV(Wz_w, 4 * 256 * 192, 160, 416, 0, 192, bfb + O_WZ1_H, bfb + O_WZ1_L);
    CONV(Wz_w, 4 * 256 * 256, 256, 416, 160, 256, bfb + O_WZ2_H, bfb + O_WZ2_L);
    CONV(Wr_w, 4 * 256 * 192, 160, 416, 0, 192, bfb + O_WR1_H, bfb + O_WR1_L);
    CONV(Wr_w, 4 * 256 * 256, 256, 416, 160, 256, bfb + O_WR2_H, bfb + O_WR2_L);
    CONV(W_w, 4 * 256 * 192, 160, 160, 0, 192, bfb + O_WW_H, bfb + O_WW_L);
    CONV(U_w, 4 * 256 * 256, 256, 256, 0, 256, bfb + O_UW_H, bfb + O_UW_L);
    CONV(mlp_w, 256 * 128, 128, 384, 0, 128, bfb + O_M1_H, bfb + O_M1_L);
    CONV(mlp_w, 256 * 256, 256, 384, 128, 256, bfb + O_M2_H, bfb + O_M2_L);
    CONV(nc1_w, 512 * 256, 256, 256, 0, 256, bfb + O_N1_H, bfb + O_N1_L);
    CONV(ec1_w, 512 * 512, 512, 512, 0, 512, bfb + O_E1_H, bfb + O_E1_L);

    const int MBE = (NE + 127) / 128;   // 938
    const int MBN = (NN + 127) / 128;   // 469
    const int MBP = (NP + 127) / 128;   // 469

    for (int l = 0; l < 4; ++l) {
        bf16* wz1H = bfb + O_WZ1_H + (size_t)l * 49152;
        bf16* wz1L = bfb + O_WZ1_L + (size_t)l * 49152;
        bf16* wz2H = bfb + O_WZ2_H + (size_t)l * 65536;
        bf16* wz2L = bfb + O_WZ2_L + (size_t)l * 65536;
        bf16* wr1H = bfb + O_WR1_H + (size_t)l * 49152;
        bf16* wr1L = bfb + O_WR1_L + (size_t)l * 49152;
        bf16* wr2H = bfb + O_WR2_H + (size_t)l * 65536;
        bf16* wr2L = bfb + O_WR2_L + (size_t)l * 65536;
        bf16* wwH  = bfb + O_WW_H + (size_t)l * 49152;
        bf16* wwL  = bfb + O_WW_L + (size_t)l * 49152;
        bf16* uwH  = bfb + O_UW_H + (size_t)l * 65536;
        bf16* uwL  = bfb + O_UW_L + (size_t)l * 65536;

        suvk<<<(NE * 64 + 255) / 256, 256>>>(nbr, sH, sL);
        gemm_tc<<<dim3(MBE, 2), 256, SMEM_DYN>>>(
            fH, fL, 192, wz1H, wz1L, sH, sL, 256, wz2H, wz2L,
            Wz_b + (size_t)l * 256, z, NE, 256, 0, nullptr, nullptr, nullptr, nullptr);
        gemm_tc<<<dim3(MBE, 2), 256, SMEM_DYN>>>(
            fH, fL, 192, wr1H, wr1L, mH, mL, 256, wr2H, wr2L,
            Wr_b + (size_t)l * 256, r, NE, 256, 0, nullptr, nullptr, nullptr, nullptr);
        rdashk<<<(NE * 64 + 255) / 256, 256>>>(nbr, rH, rL);
        gemm_tc<<<dim3(MBE, 2), 256, SMEM_DYN>>>(
            fH, fL, 192, wwH, wwL, rH, rL, 256, uwH, uwL,
            U_b + (size_t)l * 256, msg, NE, 256, 1, z, suv, mH, mL);
    }

    cudaMemsetAsync(aggr, 0, (size_t)NN * 256 * 4, 0);
    aggrk<<<(NE * 256 + 255) / 256, 256>>>(ei);
    CONV(aggr, (long long)NN * 256, 256, 256, 0, 256, aH, aL);

    gemm_tc<<<dim3(MBN, 2), 256, SMEM_DYN>>>(
        xH, xL, 128, bfb + O_M1_H, bfb + O_M1_L, aH, aL, 256, bfb + O_M2_H, bfb + O_M2_L,
        mlp_b, xg, NN, 256, 2, nullptr, nullptr, gH, gL);

    gemm_tc<<<dim3(MBN, 4), 256, SMEM_DYN>>>(
        gH, gL, 256, bfb + O_N1_H, bfb + O_N1_L, nullptr, nullptr, 0, nullptr, nullptr,
        nc1_b, h1, NN, 512, 2, nullptr, nullptr, nullptr, nullptr);
    dotk<<<(NN * 32 + 255) / 256, 256>>>(nc2_w, nc2_b, logits, NN);

    xedgek<<<(NP * 64 + 255) / 256, 256>>>(ei, eH, eL);
    gemm_tc<<<dim3(MBP, 4), 256, SMEM_DYN>>>(
        eH, eL, 512, bfb + O_E1_H, bfb + O_E1_L, nullptr, nullptr, 0, nullptr, nullptr,
        ec1_b, h1, NP, 512, 2, nullptr, nullptr, nullptr, nullptr);
    dotk<<<(NP * 32 + 255) / 256, 256>>>(ec2_w, ec2_b, logits + NN, NP);

    soft1k<<<1, 1024>>>();
    soft2k<<<(TLOG + 255) / 256, 256>>>(out);
}

// round 6
// speedup vs baseline: 2.0422x; 1.2957x over previous
#include <cuda_runtime.h>
#include <cuda_bf16.h>
#include <cstdint>
#include <math.h>

#define NN 60000
#define NE 119998
#define NP 59999
#define TLOG (NN + NP)

typedef __nv_bfloat16 bf16;

// ---------------- fp32 scratch --------------------------------------------
__device__ float g_feats[(size_t)NE * 160];
__device__ float g_msg  [(size_t)NE * 256];
__device__ float g_suv  [(size_t)NE * 256];
__device__ float g_r    [(size_t)NE * 256];
__device__ float g_z    [(size_t)NE * 256];
__device__ float g_aggr [(size_t)NN * 256];
__device__ float g_xg   [(size_t)NN * 256];
__device__ float g_h1   [(size_t)NN * 512];
__device__ float g_logits[TLOG];
__device__ float g_red[2];

// ---------------- bf16 hi/lo scratch (one big arena) -----------------------
#define SZ_FEATS ((size_t)NE * 192)
#define SZ_E256  ((size_t)NE * 256)
#define SZ_X     ((size_t)NN * 128)
#define SZ_N256  ((size_t)NN * 256)
#define SZ_XE    ((size_t)NP * 512)

constexpr size_t O_FEATS_H = 0;
constexpr size_t O_FEATS_L = O_FEATS_H + SZ_FEATS;
constexpr size_t O_MSG_H   = O_FEATS_L + SZ_FEATS;
constexpr size_t O_MSG_L   = O_MSG_H + SZ_E256;
constexpr size_t O_SUV_H   = O_MSG_L + SZ_E256;
constexpr size_t O_SUV_L   = O_SUV_H + SZ_E256;
constexpr size_t O_RD_H    = O_SUV_L + SZ_E256;
constexpr size_t O_RD_L    = O_RD_H + SZ_E256;
constexpr size_t O_X_H     = O_RD_L + SZ_E256;
constexpr size_t O_X_L     = O_X_H + SZ_X;
constexpr size_t O_AG_H    = O_X_L + SZ_X;
constexpr size_t O_AG_L    = O_AG_H + SZ_N256;
constexpr size_t O_XG_H    = O_AG_L + SZ_N256;
constexpr size_t O_XG_L    = O_XG_H + SZ_N256;
constexpr size_t O_XE_H    = O_XG_L + SZ_N256;
constexpr size_t O_XE_L    = O_XE_H + SZ_XE;
constexpr size_t O_WZ1_H   = O_XE_L + SZ_XE;
constexpr size_t O_WZ1_L   = O_WZ1_H + 4 * 256 * 192;
constexpr size_t O_WZ2_H   = O_WZ1_L + 4 * 256 * 192;
constexpr size_t O_WZ2_L   = O_WZ2_H + 4 * 256 * 256;
constexpr size_t O_WR1_H   = O_WZ2_L + 4 * 256 * 256;
constexpr size_t O_WR1_L   = O_WR1_H + 4 * 256 * 192;
constexpr size_t O_WR2_H   = O_WR1_L + 4 * 256 * 192;
constexpr size_t O_WR2_L   = O_WR2_H + 4 * 256 * 256;
constexpr size_t O_WW_H    = O_WR2_L + 4 * 256 * 256;
constexpr size_t O_WW_L    = O_WW_H + 4 * 256 * 192;
constexpr size_t O_UW_H    = O_WW_L + 4 * 256 * 192;
constexpr size_t O_UW_L    = O_UW_H + 4 * 256 * 256;
constexpr size_t O_M1_H    = O_UW_L + 4 * 256 * 256;
constexpr size_t O_M1_L    = O_M1_H + 256 * 128;
constexpr size_t O_M2_H    = O_M1_L + 256 * 128;
constexpr size_t O_M2_L    = O_M2_H + 256 * 256;
constexpr size_t O_N1_H    = O_M2_L + 256 * 256;
constexpr size_t O_N1_L    = O_N1_H + 512 * 256;
constexpr size_t O_E1_H    = O_N1_L + 512 * 256;
constexpr size_t O_E1_L    = O_E1_H + 512 * 512;
constexpr size_t BF_TOTAL  = O_E1_L + 512 * 512;

__device__ bf16 g_bf[BF_TOTAL];

// ---------------- helpers --------------------------------------------------
__device__ __forceinline__ uint32_t s2u(const void* p) {
    uint32_t a;
    asm("{ .reg .u64 t; cvta.to.shared.u64 t, %1; cvt.u32.u64 %0, t; }" : "=r"(a) : "l"(p));
    return a;
}

__device__ __forceinline__ void mma16816(float* c, const uint32_t* a, const uint32_t* b) {
    asm volatile(
        "mma.sync.aligned.m16n8k16.row.col.f32.bf16.bf16.f32 "
        "{%0,%1,%2,%3}, {%4,%5,%6,%7}, {%8,%9}, {%0,%1,%2,%3};"
        : "+f"(c[0]), "+f"(c[1]), "+f"(c[2]), "+f"(c[3])
        : "r"(a[0]), "r"(a[1]), "r"(a[2]), "r"(a[3]), "r"(b[0]), "r"(b[1]));
}

__device__ __forceinline__ void ldsm4(uint32_t* r, uint32_t addr) {
    asm volatile("ldmatrix.sync.aligned.m8n8.x4.shared.b16 {%0,%1,%2,%3}, [%4];"
                 : "=r"(r[0]), "=r"(r[1]), "=r"(r[2]), "=r"(r[3]) : "r"(addr));
}

__device__ __forceinline__ void store_hl4(bf16* hp, bf16* lp, float4 v) {
    bf16 h0 = __float2bfloat16(v.x), h1 = __float2bfloat16(v.y);
    bf16 h2 = __float2bfloat16(v.z), h3 = __float2bfloat16(v.w);
    bf16 l0 = __float2bfloat16(v.x - __bfloat162float(h0));
    bf16 l1 = __float2bfloat16(v.y - __bfloat162float(h1));
    bf16 l2 = __float2bfloat16(v.z - __bfloat162float(h2));
    bf16 l3 = __float2bfloat16(v.w - __bfloat162float(h3));
    ((__nv_bfloat162*)hp)[0] = __halves2bfloat162(h0, h1);
    ((__nv_bfloat162*)hp)[1] = __halves2bfloat162(h2, h3);
    ((__nv_bfloat162*)lp)[0] = __halves2bfloat162(l0, l1);
    ((__nv_bfloat162*)lp)[1] = __halves2bfloat162(l2, l3);
}

__device__ __forceinline__ void store_hl2(bf16* hp, bf16* lp, float v0, float v1) {
    bf16 h0 = __float2bfloat16(v0), h1 = __float2bfloat16(v1);
    bf16 l0 = __float2bfloat16(v0 - __bfloat162float(h0));
    bf16 l1 = __float2bfloat16(v1 - __bfloat162float(h1));
    *(__nv_bfloat162*)hp = __halves2bfloat162(h0, h1);
    *(__nv_bfloat162*)lp = __halves2bfloat162(l0, l1);
}

// ---------------- small kernels --------------------------------------------
__global__ void featsk(const float* __restrict__ x, const float* __restrict__ ea,
                       const int* __restrict__ ei) {
    int i = blockIdx.x * blockDim.x + threadIdx.x;
    if (i >= NE * 40) return;
    int e = i / 40;
    int q = i - e * 40;
    float4 v;
    if (q < 32) {
        int t = ei[NE + e];
        v = ((const float4*)x)[(size_t)t * 32 + q];
    } else {
        v = ((const float4*)ea)[(size_t)e * 8 + (q - 32)];
    }
    ((float4*)g_feats)[(size_t)e * 40 + q] = v;
}

__global__ void suvk(const int* __restrict__ nbr, bf16* __restrict__ sh, bf16* __restrict__ sl) {
    int i = blockIdx.x * blockDim.x + threadIdx.x;
    if (i >= NE * 64) return;
    int e = i >> 6, q = i & 63;
    const float4* m4 = (const float4*)g_msg;
    float4 acc = make_float4(0.f, 0.f, 0.f, 0.f);
#pragma unroll
    for (int j = 0; j < 3; ++j) {
        int idx = nbr[3 * (size_t)e + j];
        if (idx > 0) {
            float4 v = m4[(size_t)(idx - 1) * 64 + q];
            acc.x += v.x; acc.y += v.y; acc.z += v.z; acc.w += v.w;
        }
    }
    ((float4*)g_suv)[i] = acc;
    size_t o = (size_t)e * 256 + q * 4;
    store_hl4(sh + o, sl + o, acc);
}

__global__ void rdashk(const int* __restrict__ nbr, bf16* __restrict__ rh, bf16* __restrict__ rl) {
    int i = blockIdx.x * blockDim.x + threadIdx.x;
    if (i >= NE * 64) return;
    int e = i >> 6, q = i & 63;
    const float4* m4 = (const float4*)g_msg;
    const float4* r4 = (const float4*)g_r;
    float4 acc = make_float4(0.f, 0.f, 0.f, 0.f);
#pragma unroll
    for (int j = 0; j < 3; ++j) {
        int idx = nbr[3 * (size_t)e + j];
        if (idx > 0) {
            size_t o = (size_t)(idx - 1) * 64 + q;
            float4 g = m4[o];
            float4 rr = r4[o];
            acc.x = fmaf(rr.x, g.x, acc.x);
            acc.y = fmaf(rr.y, g.y, acc.y);
            acc.z = fmaf(rr.z, g.z, acc.z);
            acc.w = fmaf(rr.w, g.w, acc.w);
        }
    }
    size_t o = (size_t)e * 256 + q * 4;
    store_hl4(rh + o, rl + o, acc);
}

__global__ void aggrk(const int* __restrict__ ei) {
    int i = blockIdx.x * blockDim.x + threadIdx.x;
    if (i >= NE * 256) return;
    int e = i >> 8, h = i & 255;
    int t = ei[NE + e];
    atomicAdd(&g_aggr[(size_t)t * 256 + h], g_msg[i]);
}

__global__ void xedgek(const int* __restrict__ ei, bf16* __restrict__ xh, bf16* __restrict__ xl) {
    int i = blockIdx.x * blockDim.x + threadIdx.x;
    if (i >= NP * 64) return;
    int p = i >> 6, q = i & 63;
    int u = ei[2 * p];
    int v = ei[NE + 2 * p];
    const float4* X = (const float4*)g_xg;
    float4 a = X[(size_t)u * 64 + q];
    float4 b = X[(size_t)v * 64 + q];
    size_t o = (size_t)p * 512 + q * 4;
    store_hl4(xh + o, xl + o,
        make_float4(fabsf(a.x - b.x), fabsf(a.y - b.y), fabsf(a.z - b.z), fabsf(a.w - b.w)));
    store_hl4(xh + o + 256, xl + o + 256,
        make_float4(a.x + b.x, a.y + b.y, a.z + b.z, a.w + b.w));
}

// pad-convert fp32 -> bf16 hi/lo
__global__ void convk(const float* __restrict__ src, long long total, int K, int rowStride,
                      int colOff, int Kp, bf16* __restrict__ hi, bf16* __restrict__ lo) {
    long long i = (long long)blockIdx.x * blockDim.x + threadIdx.x;
    if (i >= total) return;
    int k = (int)(i % Kp);
    long long row = i / Kp;
    float v = (k < K) ? src[row * rowStride + colOff + k] : 0.f;
    bf16 h = __float2bfloat16(v);
    hi[i] = h;
    lo[i] = __float2bfloat16(v - __bfloat162float(h));
}

// ---------------- split-bf16 mma.sync GEMM (ldmatrix, 2 CTA/SM) -------------
// C[M,N] = act(A1@B1^T + A2@B2^T + bias). A,B in hi/lo bf16, K padded to 32.
// CTA tile 128(M) x 128(N), K-chunk 32, cp.async double buffer.
// mode 0=sigmoid 1=GRU 2=relu
#define KC 32
#define ROWB 80                       // 32 bf16 = 64B + 16B pad (bank stride 20)
#define TILEB (128 * ROWB)            // 10240
#define STAGE_B (4 * TILEB)           // 40960: Ah, Al, Bh, Bl
#define SMEM_DYN (2 * STAGE_B)        // 81920 -> 2 CTAs/SM

__global__ void __launch_bounds__(256, 2) gemm_tc(
    const bf16* __restrict__ A1h, const bf16* __restrict__ A1l, int K1p,
    const bf16* __restrict__ B1h, const bf16* __restrict__ B1l,
    const bf16* __restrict__ A2h, const bf16* __restrict__ A2l, int K2p,
    const bf16* __restrict__ B2h, const bf16* __restrict__ B2l,
    const float* __restrict__ bias, float* __restrict__ C, int M, int N, int mode,
    const float* __restrict__ zb, const float* __restrict__ sb,
    bf16* __restrict__ outH, bf16* __restrict__ outL)
{
    extern __shared__ char dsm[];
    const uint32_t smem_u = s2u(dsm);
    const int tid  = threadIdx.x;
    const int warp = tid >> 5;
    const int lane = tid & 31;
    const int g    = lane >> 2;
    const int t    = lane & 3;
    const int wm   = warp & 1;       // 0,1 -> 64-row half
    const int wn   = warp >> 1;      // 0..3 -> 32-col quarter
    const int m0   = blockIdx.x * 128;
    const int n0   = blockIdx.y * 128;

    const int nch1 = K1p >> 5;
    const int nch2 = B2h ? (K2p >> 5) : 0;
    const int nch  = nch1 + nch2;

    // ldmatrix lane-address offsets (bytes within a stage)
    // A x4 (16x16): m0 rows0-7 k0-7, m1 rows8-15 k0-7, m2 rows0-7 k8-15, m3 rows8-15 k8-15
    uint32_t aAddr[4], bAddr[2];
#pragma unroll
    for (int mt = 0; mt < 4; ++mt) {
        int row = wm * 64 + mt * 16 + ((lane >> 3) & 1) * 8 + (lane & 7);
        aAddr[mt] = (uint32_t)(row * ROWB + (lane >> 4) * 16);
    }
    // B x4 covers 2 n-tiles: m0 n0-7 k0-7, m1 n0-7 k8-15, m2 n8-15 k0-7, m3 n8-15 k8-15
#pragma unroll
    for (int np = 0; np < 2; ++np) {
        int row = wn * 32 + np * 16 + ((lane >> 4) & 1) * 8 + (lane & 7);
        bAddr[np] = (uint32_t)(2 * TILEB + row * ROWB + ((lane >> 3) & 1) * 16);
    }

    float acc[4][4][4];
#pragma unroll
    for (int i = 0; i < 4; ++i)
#pragma unroll
        for (int j = 0; j < 4; ++j)
#pragma unroll
            for (int k = 0; k < 4; ++k) acc[i][j][k] = 0.f;

    auto issue = [&](int c) {
        const bf16 *Ah, *Al, *Bh, *Bl;
        int lda, kc;
        if (c < nch1) { Ah = A1h; Al = A1l; Bh = B1h; Bl = B1l; lda = K1p; kc = c << 5; }
        else          { Ah = A2h; Al = A2l; Bh = B2h; Bl = B2l; lda = K2p; kc = (c - nch1) << 5; }
        char* dstb = dsm + (c & 1) * STAGE_B;
#pragma unroll
        for (int it = 0; it < 8; ++it) {
            int u = tid + it * 256;
            int which = u >> 9;            // 0 Ah, 1 Al, 2 Bh, 3 Bl
            int rem   = u & 511;
            int row   = rem >> 2;
            int seg   = rem & 3;
            const bf16* sm = (which == 0) ? Ah : (which == 1) ? Al : (which == 2) ? Bh : Bl;
            int sz = 16;
            long long grow;
            if (which < 2) {
                int gm = m0 + row;
                if (gm >= M) { gm = M - 1; sz = 0; }
                grow = gm;
            } else {
                grow = n0 + row;
            }
            const char* src = (const char*)(sm + grow * (long long)lda + kc) + seg * 16;
            uint32_t du = s2u(dstb) + (uint32_t)(which * TILEB + row * ROWB + seg * 16);
            asm volatile("cp.async.cg.shared.global [%0], [%1], 16, %2;"
                         :: "r"(du), "l"(src), "r"(sz) : "memory");
        }
        asm volatile("cp.async.commit_group;" ::: "memory");
    };

    issue(0);
    for (int c = 0; c < nch; ++c) {
        if (c + 1 < nch) {
            issue(c + 1);
            asm volatile("cp.async.wait_group 1;" ::: "memory");
        } else {
            asm volatile("cp.async.wait_group 0;" ::: "memory");
        }
        __syncthreads();

        const uint32_t base = smem_u + (c & 1) * STAGE_B;
#pragma unroll
        for (int ks = 0; ks < 2; ++ks) {
            const uint32_t ko = ks * 32;
            uint32_t ah[4][4], bh[2][4];
#pragma unroll
            for (int mt = 0; mt < 4; ++mt) ldsm4(ah[mt], base + aAddr[mt] + ko);
#pragma unroll
            for (int np = 0; np < 2; ++np) ldsm4(bh[np], base + bAddr[np] + ko);
#pragma unroll
            for (int mt = 0; mt < 4; ++mt)
#pragma unroll
                for (int nt = 0; nt < 4; ++nt)
                    mma16816(acc[mt][nt], ah[mt], &bh[nt >> 1][(nt & 1) * 2]);
            // lo(B) term: ah x bl
            {
                uint32_t bl[2][4];
#pragma unroll
                for (int np = 0; np < 2; ++np) ldsm4(bl[np], base + bAddr[np] + TILEB + ko);
#pragma unroll
                for (int mt = 0; mt < 4; ++mt)
#pragma unroll
                    for (int nt = 0; nt < 4; ++nt)
                        mma16816(acc[mt][nt], ah[mt], &bl[nt >> 1][(nt & 1) * 2]);
            }
            // lo(A) term: al x bh
            {
                uint32_t al[4][4];
#pragma unroll
                for (int mt = 0; mt < 4; ++mt) ldsm4(al[mt], base + aAddr[mt] + TILEB + ko);
#pragma unroll
                for (int mt = 0; mt < 4; ++mt)
#pragma unroll
                    for (int nt = 0; nt < 4; ++nt)
                        mma16816(acc[mt][nt], al[mt], &bh[nt >> 1][(nt & 1) * 2]);
            }
        }
        __syncthreads();
    }

    // ---------------- epilogue ----------------
#pragma unroll
    for (int mt = 0; mt < 4; ++mt) {
        int rg = m0 + wm * 64 + mt * 16 + g;
#pragma unroll
        for (int nt = 0; nt < 4; ++nt) {
            int cn = n0 + wn * 32 + nt * 8 + 2 * t;
            float b0 = bias[cn], b1 = bias[cn + 1];
#pragma unroll
            for (int h = 0; h < 2; ++h) {
                int row = rg + h * 8;
                if (row >= M) continue;
                float v0 = acc[mt][nt][2 * h]     + b0;
                float v1 = acc[mt][nt][2 * h + 1] + b1;
                size_t idx = (size_t)row * N + cn;
                if (mode == 0) {
                    v0 = 1.f / (1.f + expf(-v0));
                    v1 = 1.f / (1.f + expf(-v1));
                } else if (mode == 1) {
                    float z0 = zb[idx], z1 = zb[idx + 1];
                    v0 = (1.f - z0) * sb[idx]     + z0 * tanhf(v0);
                    v1 = (1.f - z1) * sb[idx + 1] + z1 * tanhf(v1);
                } else {
                    v0 = fmaxf(v0, 0.f);
                    v1 = fmaxf(v1, 0.f);
                }
                *(float2*)(C + idx) = make_float2(v0, v1);
                if (outH) store_hl2(outH + idx, outL + idx, v0, v1);
            }
        }
    }
}

// ---------------- head dot + softmax ---------------------------------------
__global__ void dotk(const float* __restrict__ w, const float* __restrict__ bptr,
                     float* __restrict__ out, int rows) {
    int gw = (blockIdx.x * blockDim.x + threadIdx.x) >> 5;
    int lane = threadIdx.x & 31;
    if (gw >= rows) return;
    const float* hrow = g_h1 + (size_t)gw * 512;
    float s = 0.f;
#pragma unroll
    for (int k = 0; k < 16; ++k) s = fmaf(hrow[lane + 32 * k], w[lane + 32 * k], s);
#pragma unroll
    for (int o = 16; o; o >>= 1) s += __shfl_down_sync(0xffffffffu, s, o);
    if (lane == 0) out[gw] = s + bptr[0];
}

__global__ void soft1k() {
    __shared__ float sm[1024];
    int tid = threadIdx.x;
    float mx = -1e30f;
    for (int i = tid; i < TLOG; i += 1024) mx = fmaxf(mx, g_logits[i]);
    sm[tid] = mx;
    __syncthreads();
    for (int s = 512; s > 0; s >>= 1) {
        if (tid < s) sm[tid] = fmaxf(sm[tid], sm[tid + s]);
        __syncthreads();
    }
    float gmax = sm[0];
    __syncthreads();
    float sum = 0.f;
    for (int i = tid; i < TLOG; i += 1024) sum += expf(g_logits[i] - gmax);
    sm[tid] = sum;
    __syncthreads();
    for (int s = 512; s > 0; s >>= 1) {
        if (tid < s) sm[tid] += sm[tid + s];
        __syncthreads();
    }
    if (tid == 0) { g_red[0] = gmax; g_red[1] = sm[0]; }
}

__global__ void soft2k(float* __restrict__ out) {
    int i = blockIdx.x * blockDim.x + threadIdx.x;
    if (i < TLOG) out[i] = expf(g_logits[i] - g_red[0]) / g_red[1];
}

// ---------------------------------------------------------------------------
extern "C" void kernel_launch(void* const* d_in, const int* in_sizes, int n_in,
                              void* d_out, int out_size) {
    (void)in_sizes; (void)n_in; (void)out_size;
    const float* x     = (const float*)d_in[0];
    const float* ea    = (const float*)d_in[1];
    const int*   ei    = (const int*)d_in[2];
    const int*   nbr   = (const int*)d_in[3];
    const float* Wz_w  = (const float*)d_in[4];
    const float* Wz_b  = (const float*)d_in[5];
    const float* Wr_w  = (const float*)d_in[6];
    const float* Wr_b  = (const float*)d_in[7];
    const float* W_w   = (const float*)d_in[8];
    const float* U_w   = (const float*)d_in[9];
    const float* U_b   = (const float*)d_in[10];
    const float* mlp_w = (const float*)d_in[11];
    const float* mlp_b = (const float*)d_in[12];
    const float* nc1_w = (const float*)d_in[13];
    const float* nc1_b = (const float*)d_in[14];
    const float* nc2_w = (const float*)d_in[15];
    const float* nc2_b = (const float*)d_in[16];
    const float* ec1_w = (const float*)d_in[17];
    const float* ec1_b = (const float*)d_in[18];
    const float* ec2_w = (const float*)d_in[19];
    const float* ec2_b = (const float*)d_in[20];
    float* out = (float*)d_out;

    float *feats, *msg, *suv, *r, *z, *aggr, *xg, *h1, *logits;
    bf16* bfb;
    cudaGetSymbolAddress((void**)&feats,  g_feats);
    cudaGetSymbolAddress((void**)&msg,    g_msg);
    cudaGetSymbolAddress((void**)&suv,    g_suv);
    cudaGetSymbolAddress((void**)&r,      g_r);
    cudaGetSymbolAddress((void**)&z,      g_z);
    cudaGetSymbolAddress((void**)&aggr,   g_aggr);
    cudaGetSymbolAddress((void**)&xg,     g_xg);
    cudaGetSymbolAddress((void**)&h1,     g_h1);
    cudaGetSymbolAddress((void**)&logits, g_logits);
    cudaGetSymbolAddress((void**)&bfb,    g_bf);

    cudaFuncSetAttribute(gemm_tc, cudaFuncAttributeMaxDynamicSharedMemorySize, SMEM_DYN);

    bf16 *fH = bfb + O_FEATS_H, *fL = bfb + O_FEATS_L;
    bf16 *mH = bfb + O_MSG_H,  *mL = bfb + O_MSG_L;
    bf16 *sH = bfb + O_SUV_H,  *sL = bfb + O_SUV_L;
    bf16 *rH = bfb + O_RD_H,   *rL = bfb + O_RD_L;
    bf16 *xH = bfb + O_X_H,    *xL = bfb + O_X_L;
    bf16 *aH = bfb + O_AG_H,   *aL = bfb + O_AG_L;
    bf16 *gH = bfb + O_XG_H,   *gL = bfb + O_XG_L;
    bf16 *eH = bfb + O_XE_H,   *eL = bfb + O_XE_L;

    cudaMemsetAsync(msg, 0, (size_t)NE * 256 * 4, 0);
    cudaMemsetAsync(mH, 0, SZ_E256 * 2, 0);
    cudaMemsetAsync(mL, 0, SZ_E256 * 2, 0);

    featsk<<<(NE * 40 + 255) / 256, 256>>>(x, ea, ei);

#define CONV(src, tot, K, stride, off, Kp, hi, lo) \
    convk<<<(int)(((long long)(tot) + 255) / 256), 256>>>(src, (long long)(tot), K, stride, off, Kp, hi, lo)

    CONV(feats, (long long)NE * 192, 160, 160, 0, 192, fH, fL);
    CONV(x, (long long)NN * 128, 128, 128, 0, 128, xH, xL);
    CONV(Wz_w, 4 * 256 * 192, 160, 416, 0, 192, bfb + O_WZ1_H, bfb + O_WZ1_L);
    CONV(Wz_w, 4 * 256 * 256, 256, 416, 160, 256, bfb + O_WZ2_H, bfb + O_WZ2_L);
    CONV(Wr_w, 4 * 256 * 192, 160, 416, 0, 192, bfb + O_WR1_H, bfb + O_WR1_L);
    CONV(Wr_w, 4 * 256 * 256, 256, 416, 160, 256, bfb + O_WR2_H, bfb + O_WR2_L);
    CONV(W_w, 4 * 256 * 192, 160, 160, 0, 192, bfb + O_WW_H, bfb + O_WW_L);
    CONV(U_w, 4 * 256 * 256, 256, 256, 0, 256, bfb + O_UW_H, bfb + O_UW_L);
    CONV(mlp_w, 256 * 128, 128, 384, 0, 128, bfb + O_M1_H, bfb + O_M1_L);
    CONV(mlp_w, 256 * 256, 256, 384, 128, 256, bfb + O_M2_H, bfb + O_M2_L);
    CONV(nc1_w, 512 * 256, 256, 256, 0, 256, bfb + O_N1_H, bfb + O_N1_L);
    CONV(ec1_w, 512 * 512, 512, 512, 0, 512, bfb + O_E1_H, bfb + O_E1_L);

    const int MBE = (NE + 127) / 128;   // 938
    const int MBN = (NN + 127) / 128;   // 469
    const int MBP = (NP + 127) / 128;   // 469

    for (int l = 0; l < 4; ++l) {
        bf16* wz1H = bfb + O_WZ1_H + (size_t)l * 49152;
        bf16* wz1L = bfb + O_WZ1_L + (size_t)l * 49152;
        bf16* wz2H = bfb + O_WZ2_H + (size_t)l * 65536;
        bf16* wz2L = bfb + O_WZ2_L + (size_t)l * 65536;
        bf16* wr1H = bfb + O_WR1_H + (size_t)l * 49152;
        bf16* wr1L = bfb + O_WR1_L + (size_t)l * 49152;
        bf16* wr2H = bfb + O_WR2_H + (size_t)l * 65536;
        bf16* wr2L = bfb + O_WR2_L + (size_t)l * 65536;
        bf16* wwH  = bfb + O_WW_H + (size_t)l * 49152;
        bf16* wwL  = bfb + O_WW_L + (size_t)l * 49152;
        bf16* uwH  = bfb + O_UW_H + (size_t)l * 65536;
        bf16* uwL  = bfb + O_UW_L + (size_t)l * 65536;

        suvk<<<(NE * 64 + 255) / 256, 256>>>(nbr, sH, sL);
        gemm_tc<<<dim3(MBE, 2), 256, SMEM_DYN>>>(
            fH, fL, 192, wz1H, wz1L, sH, sL, 256, wz2H, wz2L,
            Wz_b + (size_t)l * 256, z, NE, 256, 0, nullptr, nullptr, nullptr, nullptr);
        gemm_tc<<<dim3(MBE, 2), 256, SMEM_DYN>>>(
            fH, fL, 192, wr1H, wr1L, mH, mL, 256, wr2H, wr2L,
            Wr_b + (size_t)l * 256, r, NE, 256, 0, nullptr, nullptr, nullptr, nullptr);
        rdashk<<<(NE * 64 + 255) / 256, 256>>>(nbr, rH, rL);
        gemm_tc<<<dim3(MBE, 2), 256, SMEM_DYN>>>(
            fH, fL, 192, wwH, wwL, rH, rL, 256, uwH, uwL,
            U_b + (size_t)l * 256, msg, NE, 256, 1, z, suv, mH, mL);
    }

    cudaMemsetAsync(aggr, 0, (size_t)NN * 256 * 4, 0);
    aggrk<<<(NE * 256 + 255) / 256, 256>>>(ei);
    CONV(aggr, (long long)NN * 256, 256, 256, 0, 256, aH, aL);

    gemm_tc<<<dim3(MBN, 2), 256, SMEM_DYN>>>(
        xH, xL, 128, bfb + O_M1_H, bfb + O_M1_L, aH, aL, 256, bfb + O_M2_H, bfb + O_M2_L,
        mlp_b, xg, NN, 256, 2, nullptr, nullptr, gH, gL);

    gemm_tc<<<dim3(MBN, 4), 256, SMEM_DYN>>>(
        gH, gL, 256, bfb + O_N1_H, bfb + O_N1_L, nullptr, nullptr, 0, nullptr, nullptr,
        nc1_b, h1, NN, 512, 2, nullptr, nullptr, nullptr, nullptr);
    dotk<<<(NN * 32 + 255) / 256, 256>>>(nc2_w, nc2_b, logits, NN);

    xedgek<<<(NP * 64 + 255) / 256, 256>>>(ei, eH, eL);
    gemm_tc<<<dim3(MBP, 4), 256, SMEM_DYN>>>(
        eH, eL, 512, bfb + O_E1_H, bfb + O_E1_L, nullptr, nullptr, 0, nullptr, nullptr,
        ec1_b, h1, NP, 512, 2, nullptr, nullptr, nullptr, nullptr);
    dotk<<<(NP * 32 + 255) / 256, 256>>>(ec2_w, ec2_b, logits + NN, NP);

    soft1k<<<1, 1024>>>();
    soft2k<<<(TLOG + 255) / 256, 256>>>(out);
}